// round 14
// baseline (speedup 1.0000x reference)
#include <cuda_runtime.h>
#include <cuda_fp16.h>
#include <math.h>
#include <stdint.h>

#define NN 4096
#define HEADS 8
#define DH 128
#define MAXMASK 2048
// attention scale folded with log2(e): softmax done in exp2 domain
#define ATT_SCALE_L2 (0.03125f * 1.44269504f)

// ---------------- scratch (fp16 operands everywhere) ----------------
__device__ __half g_xh [(size_t)8192*1024];   // x in fp16
__device__ __half g_q  [(size_t)16*NN*DH];    // [bh][n][d], pre-scaled by 2^-5*log2e
__device__ __half g_k  [(size_t)16*NN*DH];    // [bh][n][d]
__device__ __half g_vT [(size_t)16*DH*NN];    // [bh][d][n]
__device__ __half g_att[(size_t)8192*1024];   // [b*n][dim]
__device__ __half g_wqkvT[(size_t)3072*1024]; // W_qkv^T fp16
__device__ __half g_woutT[(size_t)1024*1024]; // W_out^T fp16

// ---------------- helpers ----------------
__device__ __forceinline__ uint32_t smem_u32(const void* p) {
    uint32_t a;
    asm("{ .reg .u64 t; cvta.to.shared.u64 t, %1; cvt.u32.u64 %0, t; }"
        : "=r"(a) : "l"(p));
    return a;
}
__device__ __forceinline__ void cp16(uint32_t sdst, const void* gsrc) {
    asm volatile("cp.async.cg.shared.global [%0], [%1], 16;"
                 :: "r"(sdst), "l"(gsrc) : "memory");
}
#define CP_COMMIT() asm volatile("cp.async.commit_group;" ::: "memory")
#define CP_WAIT(n)  asm volatile("cp.async.wait_group %0;" :: "n"(n) : "memory")

__device__ __forceinline__ void ldsm4(uint32_t* r, uint32_t saddr) {
    asm volatile("ldmatrix.sync.aligned.m8n8.x4.shared.b16 {%0,%1,%2,%3}, [%4];"
        : "=r"(r[0]), "=r"(r[1]), "=r"(r[2]), "=r"(r[3]) : "r"(saddr));
}
__device__ __forceinline__ void mma16(float* d, const uint32_t* a, const uint32_t* b) {
    asm volatile(
        "mma.sync.aligned.m16n8k16.row.col.f32.f16.f16.f32 "
        "{%0,%1,%2,%3}, {%4,%5,%6,%7}, {%8,%9}, {%0,%1,%2,%3};"
        : "+f"(d[0]), "+f"(d[1]), "+f"(d[2]), "+f"(d[3])
        : "r"(a[0]), "r"(a[1]), "r"(a[2]), "r"(a[3]), "r"(b[0]), "r"(b[1]));
}
__device__ __forceinline__ uint32_t swz(int row, int slot, int rowb) {
    return (uint32_t)(row * rowb + ((slot ^ (row & 7)) << 4));
}
__device__ __forceinline__ uint32_t packh2(float a, float b) {
    __half2 h = __floats2half2_rn(a, b);
    return *(uint32_t*)&h;
}
__device__ __forceinline__ float ex2f(float x) {
    float r;
    asm("ex2.approx.ftz.f32 %0, %1;" : "=f"(r) : "f"(x));
    return r;
}

// ---------------- merged prep: conv_x + both weight transposes ----------------
// blocks [0,4096): conv x->fp16 (256 thr x 8 elems)
// blocks [4096,7168): transpose W_qkv (1024x3072 -> T), 32x32 tile
// blocks [7168,8192): transpose W_out (1024x1024 -> T)
__global__ void prep_all(const float* __restrict__ x,
                         const float* __restrict__ Wqkv,
                         const float* __restrict__ Wout,
                         __half* __restrict__ xh,
                         __half* __restrict__ wqkvT,
                         __half* __restrict__ woutT)
{
    __shared__ float t[32][33];
    const int b = blockIdx.x, tid = threadIdx.x;
    if (b < 4096) {
        size_t i = ((size_t)b * 256 + tid) * 8;
        float4 v0 = *(const float4*)(x + i);
        float4 v1 = *(const float4*)(x + i + 4);
        uint4 o;
        o.x = packh2(v0.x, v0.y); o.y = packh2(v0.z, v0.w);
        o.z = packh2(v1.x, v1.y); o.w = packh2(v1.z, v1.w);
        *(uint4*)(xh + i) = o;
        return;
    }
    const float* in;
    __half* outp;
    int R = 1024, C, bx, by;
    if (b < 7168) {
        int idx = b - 4096; in = Wqkv; outp = wqkvT; C = 3072;
        bx = (idx % 96) * 32; by = (idx / 96) * 32;
    } else {
        int idx = b - 7168; in = Wout; outp = woutT; C = 1024;
        bx = (idx % 32) * 32; by = (idx / 32) * 32;
    }
    const int tx = tid & 31, ty = tid >> 5;   // 32 x 8
#pragma unroll
    for (int i = 0; i < 32; i += 8)
        t[ty + i][tx] = in[(size_t)(by + ty + i) * C + bx + tx];
    __syncthreads();
#pragma unroll
    for (int i = 0; i < 32; i += 8)
        outp[(size_t)(bx + ty + i) * R + by + tx] = __float2half(t[tx][ty + i]);
}

// ================= fp16 GEMM (R11 2-stage, known-good) ========================
// C[M x Ncols] = A[M x 1024] * Bt[Ncols x 1024]^T ; CTA 128x128, BK=64.
#define GEMM_SMEM 65536
template<int MODE>
__global__ __launch_bounds__(256, 2) void mma_gemm(
    const __half* __restrict__ A, const __half* __restrict__ Bt,
    const float* __restrict__ bias, float* __restrict__ out)
{
    extern __shared__ char sm[];
    const uint32_t sb = smem_u32(sm);
    const int tid = threadIdx.x, lane = tid & 31, wid = tid >> 5;
    const int wm = wid >> 2, wn = wid & 3;
    const int g = lane >> 2, l4 = lane & 3;
    const int m0 = blockIdx.y * 128, col0 = blockIdx.x * 128;

    const int arow_l = lane & 15;
    const int asel = (lane >> 4) & 1;
    const int brow_l = (lane & 7) + ((lane >> 4) & 1) * 8;
    const int bsel = (lane >> 3) & 1;

    float acc[4][4][4];
#pragma unroll
    for (int mt = 0; mt < 4; mt++)
#pragma unroll
        for (int nt = 0; nt < 4; nt++)
#pragma unroll
            for (int r = 0; r < 4; r++) acc[mt][nt][r] = 0.f;

    auto fill = [&](int buf, int k0) {
#pragma unroll
        for (int i = 0; i < 2; i++) {
            int p = tid + i * 256;
            int r = p >> 2, s = (p & 3) * 2;
            cp16(sb + buf * 16384 + swz(r, s, 128),
                 A + (size_t)(m0 + r) * 1024 + k0 + s * 8);
            cp16(sb + buf * 16384 + swz(r, s + 1, 128),
                 A + (size_t)(m0 + r) * 1024 + k0 + s * 8 + 8);
        }
#pragma unroll
        for (int i = 0; i < 2; i++) {
            int p = tid + i * 256;
            int r = p >> 2, s = (p & 3) * 2;
            cp16(sb + 32768 + buf * 16384 + swz(r, s, 128),
                 Bt + (size_t)(col0 + r) * 1024 + k0 + s * 8);
            cp16(sb + 32768 + buf * 16384 + swz(r, s + 1, 128),
                 Bt + (size_t)(col0 + r) * 1024 + k0 + s * 8 + 8);
        }
    };

    fill(0, 0);
    CP_COMMIT();

    for (int kb = 0; kb < 16; kb++) {
        CP_WAIT(0);
        __syncthreads();
        if (kb < 15) { fill((kb + 1) & 1, (kb + 1) * 64); CP_COMMIT(); }
        const uint32_t ab = sb + (kb & 1) * 16384;
        const uint32_t bb = sb + 32768 + (kb & 1) * 16384;
#pragma unroll
        for (int ks = 0; ks < 4; ks++) {
            uint32_t a[4][4], b[2][4];
#pragma unroll
            for (int mt = 0; mt < 4; mt++) {
                int row = wm * 64 + mt * 16 + arow_l;
                ldsm4(a[mt], ab + swz(row, 2 * ks + asel, 128));
            }
#pragma unroll
            for (int pr = 0; pr < 2; pr++) {
                int row = wn * 32 + pr * 16 + brow_l;
                ldsm4(b[pr], bb + swz(row, 2 * ks + bsel, 128));
            }
#pragma unroll
            for (int mt = 0; mt < 4; mt++)
#pragma unroll
                for (int nt = 0; nt < 4; nt++)
                    mma16(acc[mt][nt], a[mt], &b[nt >> 1][(nt & 1) * 2]);
        }
    }

    if (MODE == 0) {
        const int which = col0 >> 10;          // 0=q 1=k 2=v
        const int h = (col0 & 1023) >> 7;
#pragma unroll
        for (int mt = 0; mt < 4; mt++)
#pragma unroll
            for (int nt = 0; nt < 4; nt++) {
                int col = col0 + wn * 32 + nt * 8 + 2 * l4;
                int dd = col & 127;
#pragma unroll
                for (int hf = 0; hf < 2; hf++) {
                    int gr = m0 + wm * 64 + mt * 16 + g + 8 * hf;
                    int bb2 = gr >> 12, n = gr & 4095;
                    int bh = bb2 * HEADS + h;
                    float c0 = acc[mt][nt][hf * 2], c1 = acc[mt][nt][hf * 2 + 1];
                    if (which == 0)     // pre-scale q by 2^-5 * log2(e)
                        *(uint32_t*)(g_q + ((size_t)bh * NN + n) * DH + dd) =
                            packh2(c0 * ATT_SCALE_L2, c1 * ATT_SCALE_L2);
                    else if (which == 1)
                        *(uint32_t*)(g_k + ((size_t)bh * NN + n) * DH + dd) = packh2(c0, c1);
                    else {
                        __half* dst = g_vT + ((size_t)bh * DH + dd) * NN + n;
                        dst[0] = __float2half(c0); dst[NN] = __float2half(c1);
                    }
                }
            }
    } else {
#pragma unroll
        for (int mt = 0; mt < 4; mt++)
#pragma unroll
            for (int nt = 0; nt < 4; nt++) {
                int col = col0 + wn * 32 + nt * 8 + 2 * l4;
                float2 bv = *(const float2*)(bias + col);
#pragma unroll
                for (int hf = 0; hf < 2; hf++) {
                    int gr = m0 + wm * 64 + mt * 16 + g + 8 * hf;
                    *(float2*)(out + (size_t)gr * 1024 + col) =
                        make_float2(acc[mt][nt][hf * 2] + bv.x,
                                    acc[mt][nt][hf * 2 + 1] + bv.y);
                }
            }
    }
}

// ================= Flash attention fp16 (R11 + mask prefetch) =================
// i-tile 64, 128 threads (4 warps), 2 CTAs/SM. Warp w owns rows 16w..16w+15.
// Q frags in registers; P register-direct; exp2 softmax; K+V double-buffered;
// mask int2s prefetched into registers BEFORE the S-MMA loop.
#define QS_OFF   0
#define K_OFF(b) (16384 + (b) * 16384)
#define V_OFF(b) (49152 + (b) * 16384)
#define ATT_SMEM 81920

__global__ __launch_bounds__(128, 2) void attn_kernel(const int* __restrict__ mask)
{
    extern __shared__ char sm[];
    const uint32_t sb = smem_u32(sm);

    const int tid = threadIdx.x, lane = tid & 31, wid = tid >> 5;
    const int g = lane >> 2, l4 = lane & 3;
    const int i0 = blockIdx.x * 64;
    const int bh = blockIdx.y;

    const __half* qP  = g_q  + (size_t)bh * NN * DH;
    const __half* kP  = g_k  + (size_t)bh * NN * DH;
    const __half* vTP = g_vT + (size_t)bh * DH * NN;

    const int arow_l = lane & 15;
    const int asel = (lane >> 4) & 1;
    const int brow_l = (lane & 7) + ((lane >> 4) & 1) * 8;
    const int bsel = (lane >> 3) & 1;

    auto fillK = [&](int buf, int j0) {           // 64 rows x 16 slots
#pragma unroll
        for (int i = 0; i < 8; i++) {
            int p = tid + i * 128;
            int r = p >> 4, s = p & 15;
            cp16(sb + K_OFF(buf) + swz(r, s, 256),
                 kP + (size_t)(j0 + r) * DH + s * 8);
        }
    };
    auto fillV = [&](int buf, int j0) {           // 128 d-rows x 8 slots
#pragma unroll
        for (int i = 0; i < 8; i++) {
            int p = tid + i * 128;
            int r = p >> 3, s = p & 7;
            cp16(sb + V_OFF(buf) + swz(r, s, 128),
                 vTP + (size_t)r * NN + j0 + s * 8);
        }
    };

    // Q fill: 64 rows x 16 slots
#pragma unroll
    for (int i = 0; i < 8; i++) {
        int p = tid + i * 128;
        int r = p >> 4, s = p & 15;
        cp16(sb + QS_OFF + swz(r, s, 256), qP + (size_t)(i0 + r) * DH + s * 8);
    }
    fillK(0, 0);
    fillV(0, 0);
    CP_COMMIT();

    uint32_t qf[8][4];   // Q fragments, resident for whole kernel
    float oacc[16][4];
#pragma unroll
    for (int nt = 0; nt < 16; nt++)
#pragma unroll
        for (int r = 0; r < 4; r++) oacc[nt][r] = 0.f;
    float mreg[2] = {-1e30f, -1e30f};
    float lreg[2] = {0.f, 0.f};

    const bool irow_masked = (i0 < MAXMASK);

    for (int jt = 0; jt < 64; jt++) {
        const int j0 = jt * 64;
        CP_WAIT(0);
        __syncthreads();

        if (jt == 0) {   // one-time: hoist Q fragments to registers
#pragma unroll
            for (int ks = 0; ks < 8; ks++)
                ldsm4(qf[ks], sb + QS_OFF + swz(wid * 16 + arow_l, 2 * ks + asel, 256));
        }
        if (jt < 63) {
            fillK((jt + 1) & 1, j0 + 64);
            fillV((jt + 1) & 1, j0 + 64);
            CP_COMMIT();
        }

        // ---- mask PREFETCH (independent loads; drain under the S MMAs) ----
        const bool domask = irow_masked && (j0 < MAXMASK);
        int2 mv[2][8];
        if (domask) {
#pragma unroll
            for (int hf = 0; hf < 2; hf++) {
                int gi = i0 + wid * 16 + g + 8 * hf;
                const int* mp = mask + (size_t)gi * MAXMASK + j0;
#pragma unroll
                for (int nt = 0; nt < 8; nt++)
                    mv[hf][nt] = *(const int2*)(mp + nt * 8 + 2 * l4);
            }
        }

        // ---- S = (Q*2^-5*log2e) K^T : 16 rows x 64 j, k=128 (8 x k16) ----
        float sacc[8][4];
#pragma unroll
        for (int nt = 0; nt < 8; nt++)
#pragma unroll
            for (int r = 0; r < 4; r++) sacc[nt][r] = 0.f;

        const uint32_t kb = sb + K_OFF(jt & 1);
#pragma unroll
        for (int ks = 0; ks < 8; ks++) {
            uint32_t b[4][4];
#pragma unroll
            for (int pr = 0; pr < 4; pr++)
                ldsm4(b[pr], kb + swz(pr * 16 + brow_l, 2 * ks + bsel, 256));
#pragma unroll
            for (int nt = 0; nt < 8; nt++)
                mma16(sacc[nt], qf[ks], &b[nt >> 1][(nt & 1) * 2]);
        }

        // ---- apply mask (registers, no memory latency here) ----
        if (domask) {
#pragma unroll
            for (int hf = 0; hf < 2; hf++)
#pragma unroll
                for (int nt = 0; nt < 8; nt++) {
                    if (mv[hf][nt].x == 0) sacc[nt][hf * 2]     = -INFINITY;
                    if (mv[hf][nt].y == 0) sacc[nt][hf * 2 + 1] = -INFINITY;
                }
        }

        // ---- softmax (exp2 domain), P stays in registers ----
#pragma unroll
        for (int hf = 0; hf < 2; hf++) {
            float pm = -INFINITY;
#pragma unroll
            for (int nt = 0; nt < 8; nt++)
                pm = fmaxf(pm, fmaxf(sacc[nt][hf * 2], sacc[nt][hf * 2 + 1]));
            pm = fmaxf(pm, __shfl_xor_sync(0xffffffffu, pm, 1));
            pm = fmaxf(pm, __shfl_xor_sync(0xffffffffu, pm, 2));
            float mc = fmaxf(fmaxf(mreg[hf], pm), -1e30f);
            float corr = ex2f(mreg[hf] - mc);
            mreg[hf] = mc;
            float rs = 0.f;
#pragma unroll
            for (int nt = 0; nt < 8; nt++) {
                float p0 = ex2f(sacc[nt][hf * 2]     - mc);
                float p1 = ex2f(sacc[nt][hf * 2 + 1] - mc);
                sacc[nt][hf * 2] = p0; sacc[nt][hf * 2 + 1] = p1;
                rs += p0 + p1;
            }
            rs += __shfl_xor_sync(0xffffffffu, rs, 1);
            rs += __shfl_xor_sync(0xffffffffu, rs, 2);
            lreg[hf] = lreg[hf] * corr + rs;
            if (__any_sync(0xffffffffu, corr != 1.0f)) {
#pragma unroll
                for (int nt = 0; nt < 16; nt++) {
                    oacc[nt][hf * 2]     *= corr;
                    oacc[nt][hf * 2 + 1] *= corr;
                }
            }
        }

        // ---- P C-fragments -> A-fragments (pure register pack) ----
        uint32_t pa[4][4];
#pragma unroll
        for (int ks2 = 0; ks2 < 4; ks2++) {
            pa[ks2][0] = packh2(sacc[2 * ks2][0],     sacc[2 * ks2][1]);
            pa[ks2][1] = packh2(sacc[2 * ks2][2],     sacc[2 * ks2][3]);
            pa[ks2][2] = packh2(sacc[2 * ks2 + 1][0], sacc[2 * ks2 + 1][1]);
            pa[ks2][3] = packh2(sacc[2 * ks2 + 1][2], sacc[2 * ks2 + 1][3]);
        }

        // ---- O += P V : 16 rows x 128 d, k=64 (4 x k16) ----
        const uint32_t vb = sb + V_OFF(jt & 1);
#pragma unroll
        for (int ks2 = 0; ks2 < 4; ks2++) {
            uint32_t b[8][4];
#pragma unroll
            for (int pr = 0; pr < 8; pr++)
                ldsm4(b[pr], vb + swz(pr * 16 + brow_l, 2 * ks2 + bsel, 128));
#pragma unroll
            for (int nt = 0; nt < 16; nt++)
                mma16(oacc[nt], pa[ks2], &b[nt >> 1][(nt & 1) * 2]);
        }
    }

    // ---- finalize (fp16 for out-proj consumption) ----
    const int b = bh >> 3, h = bh & 7;
#pragma unroll
    for (int hf = 0; hf < 2; hf++) {
        float inv = 1.f / lreg[hf];
        int gi = i0 + wid * 16 + g + 8 * hf;
        size_t base = ((size_t)(b * NN + gi)) * 1024 + h * DH;
#pragma unroll
        for (int nt = 0; nt < 16; nt++)
            *(uint32_t*)(g_att + base + nt * 8 + 2 * l4) =
                packh2(oacc[nt][hf * 2] * inv, oacc[nt][hf * 2 + 1] * inv);
    }
}

// ---------------- launcher ----------------
extern "C" void kernel_launch(void* const* d_in, const int* in_sizes, int n_in,
                              void* d_out, int out_size)
{
    const float* x     = (const float*)d_in[0];
    const float* W_qkv = (const float*)d_in[1];
    const float* W_out = (const float*)d_in[2];
    const float* b_out = (const float*)d_in[3];
    const int*   mask  = (const int*)  d_in[4];
    float* out = (float*)d_out;

    cudaFuncSetAttribute(attn_kernel,
                         cudaFuncAttributeMaxDynamicSharedMemorySize, ATT_SMEM);
    cudaFuncSetAttribute(mma_gemm<0>,
                         cudaFuncAttributeMaxDynamicSharedMemorySize, GEMM_SMEM);
    cudaFuncSetAttribute(mma_gemm<1>,
                         cudaFuncAttributeMaxDynamicSharedMemorySize, GEMM_SMEM);

    __half* xh;    cudaGetSymbolAddress((void**)&xh, g_xh);
    __half* wqkvT; cudaGetSymbolAddress((void**)&wqkvT, g_wqkvT);
    __half* woutT; cudaGetSymbolAddress((void**)&woutT, g_woutT);
    __half* att;   cudaGetSymbolAddress((void**)&att, g_att);

    prep_all<<<8192, 256>>>(x, W_qkv, W_out, xh, wqkvT, woutT);

    mma_gemm<0><<<dim3(24, 64), 256, GEMM_SMEM>>>(xh, wqkvT, nullptr, nullptr);
    attn_kernel<<<dim3(64, 16), 128, ATT_SMEM>>>(mask);
    mma_gemm<1><<<dim3(8, 64), 256, GEMM_SMEM>>>(att, woutT, b_out, out);
}

// round 15
// speedup vs baseline: 1.0045x; 1.0045x over previous
#include <cuda_runtime.h>
#include <cuda_fp16.h>
#include <math.h>
#include <stdint.h>

#define NN 4096
#define HEADS 8
#define DH 128
#define MAXMASK 2048
// attention scale folded with log2(e): softmax done in exp2 domain
#define ATT_SCALE_L2 (0.03125f * 1.44269504f)

// ---------------- scratch (fp16 operands everywhere) ----------------
__device__ __half g_xh [(size_t)8192*1024];   // x in fp16
__device__ __half g_q  [(size_t)16*NN*DH];    // [bh][n][d], pre-scaled by 2^-5*log2e
__device__ __half g_k  [(size_t)16*NN*DH];    // [bh][n][d]
__device__ __half g_vT [(size_t)16*DH*NN];    // [bh][d][n]
__device__ __half g_att[(size_t)8192*1024];   // [b*n][dim]
__device__ __half g_wqkvT[(size_t)3072*1024]; // W_qkv^T fp16
__device__ __half g_woutT[(size_t)1024*1024]; // W_out^T fp16

// ---------------- helpers ----------------
__device__ __forceinline__ uint32_t smem_u32(const void* p) {
    uint32_t a;
    asm("{ .reg .u64 t; cvta.to.shared.u64 t, %1; cvt.u32.u64 %0, t; }"
        : "=r"(a) : "l"(p));
    return a;
}
__device__ __forceinline__ void cp16(uint32_t sdst, const void* gsrc) {
    asm volatile("cp.async.cg.shared.global [%0], [%1], 16;"
                 :: "r"(sdst), "l"(gsrc) : "memory");
}
#define CP_COMMIT() asm volatile("cp.async.commit_group;" ::: "memory")
#define CP_WAIT(n)  asm volatile("cp.async.wait_group %0;" :: "n"(n) : "memory")

__device__ __forceinline__ void ldsm4(uint32_t* r, uint32_t saddr) {
    asm volatile("ldmatrix.sync.aligned.m8n8.x4.shared.b16 {%0,%1,%2,%3}, [%4];"
        : "=r"(r[0]), "=r"(r[1]), "=r"(r[2]), "=r"(r[3]) : "r"(saddr));
}
__device__ __forceinline__ void mma16(float* d, const uint32_t* a, const uint32_t* b) {
    asm volatile(
        "mma.sync.aligned.m16n8k16.row.col.f32.f16.f16.f32 "
        "{%0,%1,%2,%3}, {%4,%5,%6,%7}, {%8,%9}, {%0,%1,%2,%3};"
        : "+f"(d[0]), "+f"(d[1]), "+f"(d[2]), "+f"(d[3])
        : "r"(a[0]), "r"(a[1]), "r"(a[2]), "r"(a[3]), "r"(b[0]), "r"(b[1]));
}
__device__ __forceinline__ uint32_t swz(int row, int slot, int rowb) {
    return (uint32_t)(row * rowb + ((slot ^ (row & 7)) << 4));
}
__device__ __forceinline__ uint32_t packh2(float a, float b) {
    __half2 h = __floats2half2_rn(a, b);
    return *(uint32_t*)&h;
}
__device__ __forceinline__ float ex2f(float x) {
    float r;
    asm("ex2.approx.ftz.f32 %0, %1;" : "=f"(r) : "f"(x));
    return r;
}
// exp2 on a packed half2 (one MUFU op for two values)
__device__ __forceinline__ uint32_t ex2h2(uint32_t x) {
    uint32_t r;
    asm("ex2.approx.f16x2 %0, %1;" : "=r"(r) : "r"(x));
    return r;
}

// ---------------- convert x to fp16 ----------------
__global__ void conv_x(const float* __restrict__ in, __half* __restrict__ outp)
{
    size_t i = ((size_t)blockIdx.x * blockDim.x + threadIdx.x) * 8;
    float4 v0 = *(const float4*)(in + i);
    float4 v1 = *(const float4*)(in + i + 4);
    uint4 o;
    o.x = packh2(v0.x, v0.y); o.y = packh2(v0.z, v0.w);
    o.z = packh2(v1.x, v1.y); o.w = packh2(v1.z, v1.w);
    *(uint4*)(outp + i) = o;
}

// ---------------- weight transpose + fp16 convert ----------------
__global__ void transpose_k(const float* __restrict__ in, __half* __restrict__ outp,
                            int R, int C)
{
    __shared__ float t[32][33];
    int bx = blockIdx.x * 32, by = blockIdx.y * 32;
    int tx = threadIdx.x, ty = threadIdx.y;  // 32 x 8
#pragma unroll
    for (int i = 0; i < 32; i += 8)
        t[ty + i][tx] = in[(size_t)(by + ty + i) * C + bx + tx];
    __syncthreads();
#pragma unroll
    for (int i = 0; i < 32; i += 8)
        outp[(size_t)(bx + ty + i) * R + by + tx] = __float2half(t[tx][ty + i]);
}

// ================= fp16 GEMM (R11 2-stage, known-good) ========================
#define GEMM_SMEM 65536
template<int MODE>
__global__ __launch_bounds__(256, 2) void mma_gemm(
    const __half* __restrict__ A, const __half* __restrict__ Bt,
    const float* __restrict__ bias, float* __restrict__ out)
{
    extern __shared__ char sm[];
    const uint32_t sb = smem_u32(sm);
    const int tid = threadIdx.x, lane = tid & 31, wid = tid >> 5;
    const int wm = wid >> 2, wn = wid & 3;
    const int g = lane >> 2, l4 = lane & 3;
    const int m0 = blockIdx.y * 128, col0 = blockIdx.x * 128;

    const int arow_l = lane & 15;
    const int asel = (lane >> 4) & 1;
    const int brow_l = (lane & 7) + ((lane >> 4) & 1) * 8;
    const int bsel = (lane >> 3) & 1;

    float acc[4][4][4];
#pragma unroll
    for (int mt = 0; mt < 4; mt++)
#pragma unroll
        for (int nt = 0; nt < 4; nt++)
#pragma unroll
            for (int r = 0; r < 4; r++) acc[mt][nt][r] = 0.f;

    auto fill = [&](int buf, int k0) {
#pragma unroll
        for (int i = 0; i < 2; i++) {
            int p = tid + i * 256;
            int r = p >> 2, s = (p & 3) * 2;
            cp16(sb + buf * 16384 + swz(r, s, 128),
                 A + (size_t)(m0 + r) * 1024 + k0 + s * 8);
            cp16(sb + buf * 16384 + swz(r, s + 1, 128),
                 A + (size_t)(m0 + r) * 1024 + k0 + s * 8 + 8);
        }
#pragma unroll
        for (int i = 0; i < 2; i++) {
            int p = tid + i * 256;
            int r = p >> 2, s = (p & 3) * 2;
            cp16(sb + 32768 + buf * 16384 + swz(r, s, 128),
                 Bt + (size_t)(col0 + r) * 1024 + k0 + s * 8);
            cp16(sb + 32768 + buf * 16384 + swz(r, s + 1, 128),
                 Bt + (size_t)(col0 + r) * 1024 + k0 + s * 8 + 8);
        }
    };

    fill(0, 0);
    CP_COMMIT();

    for (int kb = 0; kb < 16; kb++) {
        CP_WAIT(0);
        __syncthreads();
        if (kb < 15) { fill((kb + 1) & 1, (kb + 1) * 64); CP_COMMIT(); }
        const uint32_t ab = sb + (kb & 1) * 16384;
        const uint32_t bb = sb + 32768 + (kb & 1) * 16384;
#pragma unroll
        for (int ks = 0; ks < 4; ks++) {
            uint32_t a[4][4], b[2][4];
#pragma unroll
            for (int mt = 0; mt < 4; mt++) {
                int row = wm * 64 + mt * 16 + arow_l;
                ldsm4(a[mt], ab + swz(row, 2 * ks + asel, 128));
            }
#pragma unroll
            for (int pr = 0; pr < 2; pr++) {
                int row = wn * 32 + pr * 16 + brow_l;
                ldsm4(b[pr], bb + swz(row, 2 * ks + bsel, 128));
            }
#pragma unroll
            for (int mt = 0; mt < 4; mt++)
#pragma unroll
                for (int nt = 0; nt < 4; nt++)
                    mma16(acc[mt][nt], a[mt], &b[nt >> 1][(nt & 1) * 2]);
        }
    }

    if (MODE == 0) {
        const int which = col0 >> 10;          // 0=q 1=k 2=v
        const int h = (col0 & 1023) >> 7;
#pragma unroll
        for (int mt = 0; mt < 4; mt++)
#pragma unroll
            for (int nt = 0; nt < 4; nt++) {
                int col = col0 + wn * 32 + nt * 8 + 2 * l4;
                int dd = col & 127;
#pragma unroll
                for (int hf = 0; hf < 2; hf++) {
                    int gr = m0 + wm * 64 + mt * 16 + g + 8 * hf;
                    int bb2 = gr >> 12, n = gr & 4095;
                    int bh = bb2 * HEADS + h;
                    float c0 = acc[mt][nt][hf * 2], c1 = acc[mt][nt][hf * 2 + 1];
                    if (which == 0)     // pre-scale q by 2^-5 * log2(e)
                        *(uint32_t*)(g_q + ((size_t)bh * NN + n) * DH + dd) =
                            packh2(c0 * ATT_SCALE_L2, c1 * ATT_SCALE_L2);
                    else if (which == 1)
                        *(uint32_t*)(g_k + ((size_t)bh * NN + n) * DH + dd) = packh2(c0, c1);
                    else {
                        __half* dst = g_vT + ((size_t)bh * DH + dd) * NN + n;
                        dst[0] = __float2half(c0); dst[NN] = __float2half(c1);
                    }
                }
            }
    } else {
#pragma unroll
        for (int mt = 0; mt < 4; mt++)
#pragma unroll
            for (int nt = 0; nt < 4; nt++) {
                int col = col0 + wn * 32 + nt * 8 + 2 * l4;
                float2 bv = *(const float2*)(bias + col);
#pragma unroll
                for (int hf = 0; hf < 2; hf++) {
                    int gr = m0 + wm * 64 + mt * 16 + g + 8 * hf;
                    *(float2*)(out + (size_t)gr * 1024 + col) =
                        make_float2(acc[mt][nt][hf * 2] + bv.x,
                                    acc[mt][nt][hf * 2 + 1] + bv.y);
                }
            }
    }
}

// ================= Flash attention fp16 (R11 + h2exp2 softmax) ================
// i-tile 64, 128 threads (4 warps), 2 CTAs/SM. Warp w owns rows 16w..16w+15.
// Q frags in registers; P register-direct via ex2.approx.f16x2 (pack-then-exp);
// K+V double-buffered.
#define QS_OFF   0
#define K_OFF(b) (16384 + (b) * 16384)
#define V_OFF(b) (49152 + (b) * 16384)
#define ATT_SMEM 81920

__global__ __launch_bounds__(128, 2) void attn_kernel(const int* __restrict__ mask)
{
    extern __shared__ char sm[];
    const uint32_t sb = smem_u32(sm);

    const int tid = threadIdx.x, lane = tid & 31, wid = tid >> 5;
    const int g = lane >> 2, l4 = lane & 3;
    const int i0 = blockIdx.x * 64;
    const int bh = blockIdx.y;

    const __half* qP  = g_q  + (size_t)bh * NN * DH;
    const __half* kP  = g_k  + (size_t)bh * NN * DH;
    const __half* vTP = g_vT + (size_t)bh * DH * NN;

    const int arow_l = lane & 15;
    const int asel = (lane >> 4) & 1;
    const int brow_l = (lane & 7) + ((lane >> 4) & 1) * 8;
    const int bsel = (lane >> 3) & 1;

    auto fillK = [&](int buf, int j0) {           // 64 rows x 16 slots
#pragma unroll
        for (int i = 0; i < 8; i++) {
            int p = tid + i * 128;
            int r = p >> 4, s = p & 15;
            cp16(sb + K_OFF(buf) + swz(r, s, 256),
                 kP + (size_t)(j0 + r) * DH + s * 8);
        }
    };
    auto fillV = [&](int buf, int j0) {           // 128 d-rows x 8 slots
#pragma unroll
        for (int i = 0; i < 8; i++) {
            int p = tid + i * 128;
            int r = p >> 3, s = p & 7;
            cp16(sb + V_OFF(buf) + swz(r, s, 128),
                 vTP + (size_t)r * NN + j0 + s * 8);
        }
    };

    // Q fill: 64 rows x 16 slots
#pragma unroll
    for (int i = 0; i < 8; i++) {
        int p = tid + i * 128;
        int r = p >> 4, s = p & 15;
        cp16(sb + QS_OFF + swz(r, s, 256), qP + (size_t)(i0 + r) * DH + s * 8);
    }
    fillK(0, 0);
    fillV(0, 0);
    CP_COMMIT();

    uint32_t qf[8][4];   // Q fragments, resident for whole kernel
    float oacc[16][4];
#pragma unroll
    for (int nt = 0; nt < 16; nt++)
#pragma unroll
        for (int r = 0; r < 4; r++) oacc[nt][r] = 0.f;
    float mreg[2] = {-1e30f, -1e30f};
    float lreg[2] = {0.f, 0.f};

    for (int jt = 0; jt < 64; jt++) {
        const int j0 = jt * 64;
        CP_WAIT(0);
        __syncthreads();

        if (jt == 0) {   // one-time: hoist Q fragments to registers
#pragma unroll
            for (int ks = 0; ks < 8; ks++)
                ldsm4(qf[ks], sb + QS_OFF + swz(wid * 16 + arow_l, 2 * ks + asel, 256));
        }
        if (jt < 63) {
            fillK((jt + 1) & 1, j0 + 64);
            fillV((jt + 1) & 1, j0 + 64);
            CP_COMMIT();
        }

        // ---- S = (Q*2^-5*log2e) K^T : 16 rows x 64 j, k=128 (8 x k16) ----
        float sacc[8][4];
#pragma unroll
        for (int nt = 0; nt < 8; nt++)
#pragma unroll
            for (int r = 0; r < 4; r++) sacc[nt][r] = 0.f;

        const uint32_t kb = sb + K_OFF(jt & 1);
#pragma unroll
        for (int ks = 0; ks < 8; ks++) {
            uint32_t b[4][4];
#pragma unroll
            for (int pr = 0; pr < 4; pr++)
                ldsm4(b[pr], kb + swz(pr * 16 + brow_l, 2 * ks + bsel, 256));
#pragma unroll
            for (int nt = 0; nt < 8; nt++)
                mma16(sacc[nt], qf[ks], &b[nt >> 1][(nt & 1) * 2]);
        }

        // ---- mask (S in log2 domain) ----
        if (i0 < MAXMASK && j0 < MAXMASK) {
#pragma unroll
            for (int hf = 0; hf < 2; hf++) {
                int gi = i0 + wid * 16 + g + 8 * hf;
                const int* mp = mask + (size_t)gi * MAXMASK + j0;
#pragma unroll
                for (int nt = 0; nt < 8; nt++) {
                    int2 mv = *(const int2*)(mp + nt * 8 + 2 * l4);
                    if (mv.x == 0) sacc[nt][hf * 2]     = -INFINITY;
                    if (mv.y == 0) sacc[nt][hf * 2 + 1] = -INFINITY;
                }
            }
        }

        // ---- softmax (exp2 domain): pack (s-mc) to half2, ONE ex2.f16x2 per
        //      pair -> result IS the PV A-fragment half2. rs recovered in fp32.
        uint32_t pa[4][4];
#pragma unroll
        for (int hf = 0; hf < 2; hf++) {
            float pm = -INFINITY;
#pragma unroll
            for (int nt = 0; nt < 8; nt++)
                pm = fmaxf(pm, fmaxf(sacc[nt][hf * 2], sacc[nt][hf * 2 + 1]));
            pm = fmaxf(pm, __shfl_xor_sync(0xffffffffu, pm, 1));
            pm = fmaxf(pm, __shfl_xor_sync(0xffffffffu, pm, 2));
            float mc = fmaxf(fmaxf(mreg[hf], pm), -1e30f);
            float corr = ex2f(mreg[hf] - mc);
            mreg[hf] = mc;
            float rs = 0.f;
#pragma unroll
            for (int nt = 0; nt < 8; nt++) {
                uint32_t ph = ex2h2(packh2(sacc[nt][hf * 2]     - mc,
                                           sacc[nt][hf * 2 + 1] - mc));
                pa[nt >> 1][2 * (nt & 1) + hf] = ph;
                float2 f = __half22float2(*(__half2*)&ph);
                rs += f.x + f.y;
            }
            rs += __shfl_xor_sync(0xffffffffu, rs, 1);
            rs += __shfl_xor_sync(0xffffffffu, rs, 2);
            lreg[hf] = lreg[hf] * corr + rs;
            if (__any_sync(0xffffffffu, corr != 1.0f)) {
#pragma unroll
                for (int nt = 0; nt < 16; nt++) {
                    oacc[nt][hf * 2]     *= corr;
                    oacc[nt][hf * 2 + 1] *= corr;
                }
            }
        }

        // ---- O += P V : 16 rows x 128 d, k=64 (4 x k16) ----
        const uint32_t vb = sb + V_OFF(jt & 1);
#pragma unroll
        for (int ks2 = 0; ks2 < 4; ks2++) {
            uint32_t b[8][4];
#pragma unroll
            for (int pr = 0; pr < 8; pr++)
                ldsm4(b[pr], vb + swz(pr * 16 + brow_l, 2 * ks2 + bsel, 128));
#pragma unroll
            for (int nt = 0; nt < 16; nt++)
                mma16(oacc[nt], pa[ks2], &b[nt >> 1][(nt & 1) * 2]);
        }
    }

    // ---- finalize (fp16 for out-proj consumption) ----
    const int b = bh >> 3, h = bh & 7;
#pragma unroll
    for (int hf = 0; hf < 2; hf++) {
        float inv = 1.f / lreg[hf];
        int gi = i0 + wid * 16 + g + 8 * hf;
        size_t base = ((size_t)(b * NN + gi)) * 1024 + h * DH;
#pragma unroll
        for (int nt = 0; nt < 16; nt++)
            *(uint32_t*)(g_att + base + nt * 8 + 2 * l4) =
                packh2(oacc[nt][hf * 2] * inv, oacc[nt][hf * 2 + 1] * inv);
    }
}

// ---------------- launcher ----------------
extern "C" void kernel_launch(void* const* d_in, const int* in_sizes, int n_in,
                              void* d_out, int out_size)
{
    const float* x     = (const float*)d_in[0];
    const float* W_qkv = (const float*)d_in[1];
    const float* W_out = (const float*)d_in[2];
    const float* b_out = (const float*)d_in[3];
    const int*   mask  = (const int*)  d_in[4];
    float* out = (float*)d_out;

    cudaFuncSetAttribute(attn_kernel,
                         cudaFuncAttributeMaxDynamicSharedMemorySize, ATT_SMEM);
    cudaFuncSetAttribute(mma_gemm<0>,
                         cudaFuncAttributeMaxDynamicSharedMemorySize, GEMM_SMEM);
    cudaFuncSetAttribute(mma_gemm<1>,
                         cudaFuncAttributeMaxDynamicSharedMemorySize, GEMM_SMEM);

    __half* xh;    cudaGetSymbolAddress((void**)&xh, g_xh);
    __half* wqkvT; cudaGetSymbolAddress((void**)&wqkvT, g_wqkvT);
    __half* woutT; cudaGetSymbolAddress((void**)&woutT, g_woutT);
    __half* att;   cudaGetSymbolAddress((void**)&att, g_att);

    conv_x<<<4096, 256>>>(x, xh);
    transpose_k<<<dim3(96, 32), dim3(32, 8)>>>(W_qkv, wqkvT, 1024, 3072);
    transpose_k<<<dim3(32, 32), dim3(32, 8)>>>(W_out, woutT, 1024, 1024);

    mma_gemm<0><<<dim3(24, 64), 256, GEMM_SMEM>>>(xh, wqkvT, nullptr, nullptr);
    attn_kernel<<<dim3(64, 16), 128, ATT_SMEM>>>(mask);
    mma_gemm<1><<<dim3(8, 64), 256, GEMM_SMEM>>>(att, woutT, b_out, out);
}

// round 16
// speedup vs baseline: 1.0073x; 1.0028x over previous
#include <cuda_runtime.h>
#include <cuda_fp16.h>
#include <math.h>
#include <stdint.h>

#define NN 4096
#define HEADS 8
#define DH 128
#define MAXMASK 2048
// attention scale folded with log2(e): softmax done in exp2 domain
#define ATT_SCALE_L2 (0.03125f * 1.44269504f)

// ---------------- scratch (fp16 operands everywhere) ----------------
__device__ __half g_xh [(size_t)8192*1024];   // x in fp16
__device__ __half g_q  [(size_t)16*NN*DH];    // [bh][n][d], pre-scaled by 2^-5*log2e
__device__ __half g_k  [(size_t)16*NN*DH];    // [bh][n][d]
__device__ __half g_v  [(size_t)16*NN*DH];    // [bh][n][d] (row-major; trans at ldsm)
__device__ __half g_att[(size_t)8192*1024];   // [b*n][dim]
__device__ __half g_wqkvT[(size_t)3072*1024]; // W_qkv^T fp16
__device__ __half g_woutT[(size_t)1024*1024]; // W_out^T fp16

// ---------------- helpers ----------------
__device__ __forceinline__ uint32_t smem_u32(const void* p) {
    uint32_t a;
    asm("{ .reg .u64 t; cvta.to.shared.u64 t, %1; cvt.u32.u64 %0, t; }"
        : "=r"(a) : "l"(p));
    return a;
}
__device__ __forceinline__ void cp16(uint32_t sdst, const void* gsrc) {
    asm volatile("cp.async.cg.shared.global [%0], [%1], 16;"
                 :: "r"(sdst), "l"(gsrc) : "memory");
}
#define CP_COMMIT() asm volatile("cp.async.commit_group;" ::: "memory")
#define CP_WAIT(n)  asm volatile("cp.async.wait_group %0;" :: "n"(n) : "memory")

__device__ __forceinline__ void ldsm4(uint32_t* r, uint32_t saddr) {
    asm volatile("ldmatrix.sync.aligned.m8n8.x4.shared.b16 {%0,%1,%2,%3}, [%4];"
        : "=r"(r[0]), "=r"(r[1]), "=r"(r[2]), "=r"(r[3]) : "r"(saddr));
}
__device__ __forceinline__ void ldsm4t(uint32_t* r, uint32_t saddr) {
    asm volatile("ldmatrix.sync.aligned.m8n8.x4.trans.shared.b16 {%0,%1,%2,%3}, [%4];"
        : "=r"(r[0]), "=r"(r[1]), "=r"(r[2]), "=r"(r[3]) : "r"(saddr));
}
__device__ __forceinline__ void mma16(float* d, const uint32_t* a, const uint32_t* b) {
    asm volatile(
        "mma.sync.aligned.m16n8k16.row.col.f32.f16.f16.f32 "
        "{%0,%1,%2,%3}, {%4,%5,%6,%7}, {%8,%9}, {%0,%1,%2,%3};"
        : "+f"(d[0]), "+f"(d[1]), "+f"(d[2]), "+f"(d[3])
        : "r"(a[0]), "r"(a[1]), "r"(a[2]), "r"(a[3]), "r"(b[0]), "r"(b[1]));
}
__device__ __forceinline__ uint32_t swz(int row, int slot, int rowb) {
    return (uint32_t)(row * rowb + ((slot ^ (row & 7)) << 4));
}
__device__ __forceinline__ uint32_t packh2(float a, float b) {
    __half2 h = __floats2half2_rn(a, b);
    return *(uint32_t*)&h;
}
__device__ __forceinline__ float ex2f(float x) {
    float r;
    asm("ex2.approx.ftz.f32 %0, %1;" : "=f"(r) : "f"(x));
    return r;
}

// ---------------- convert x to fp16 ----------------
__global__ void conv_x(const float* __restrict__ in, __half* __restrict__ outp)
{
    size_t i = ((size_t)blockIdx.x * blockDim.x + threadIdx.x) * 8;
    float4 v0 = *(const float4*)(in + i);
    float4 v1 = *(const float4*)(in + i + 4);
    uint4 o;
    o.x = packh2(v0.x, v0.y); o.y = packh2(v0.z, v0.w);
    o.z = packh2(v1.x, v1.y); o.w = packh2(v1.z, v1.w);
    *(uint4*)(outp + i) = o;
}

// ---------------- weight transpose + fp16 convert ----------------
__global__ void transpose_k(const float* __restrict__ in, __half* __restrict__ outp,
                            int R, int C)
{
    __shared__ float t[32][33];
    int bx = blockIdx.x * 32, by = blockIdx.y * 32;
    int tx = threadIdx.x, ty = threadIdx.y;  // 32 x 8
#pragma unroll
    for (int i = 0; i < 32; i += 8)
        t[ty + i][tx] = in[(size_t)(by + ty + i) * C + bx + tx];
    __syncthreads();
#pragma unroll
    for (int i = 0; i < 32; i += 8)
        outp[(size_t)(bx + ty + i) * R + by + tx] = __float2half(t[tx][ty + i]);
}

// ================= fp16 GEMM (R11 2-stage, known-good) ========================
#define GEMM_SMEM 65536
template<int MODE>
__global__ __launch_bounds__(256, 2) void mma_gemm(
    const __half* __restrict__ A, const __half* __restrict__ Bt,
    const float* __restrict__ bias, float* __restrict__ out)
{
    extern __shared__ char sm[];
    const uint32_t sb = smem_u32(sm);
    const int tid = threadIdx.x, lane = tid & 31, wid = tid >> 5;
    const int wm = wid >> 2, wn = wid & 3;
    const int g = lane >> 2, l4 = lane & 3;
    const int m0 = blockIdx.y * 128, col0 = blockIdx.x * 128;

    const int arow_l = lane & 15;
    const int asel = (lane >> 4) & 1;
    const int brow_l = (lane & 7) + ((lane >> 4) & 1) * 8;
    const int bsel = (lane >> 3) & 1;

    float acc[4][4][4];
#pragma unroll
    for (int mt = 0; mt < 4; mt++)
#pragma unroll
        for (int nt = 0; nt < 4; nt++)
#pragma unroll
            for (int r = 0; r < 4; r++) acc[mt][nt][r] = 0.f;

    auto fill = [&](int buf, int k0) {
#pragma unroll
        for (int i = 0; i < 2; i++) {
            int p = tid + i * 256;
            int r = p >> 2, s = (p & 3) * 2;
            cp16(sb + buf * 16384 + swz(r, s, 128),
                 A + (size_t)(m0 + r) * 1024 + k0 + s * 8);
            cp16(sb + buf * 16384 + swz(r, s + 1, 128),
                 A + (size_t)(m0 + r) * 1024 + k0 + s * 8 + 8);
        }
#pragma unroll
        for (int i = 0; i < 2; i++) {
            int p = tid + i * 256;
            int r = p >> 2, s = (p & 3) * 2;
            cp16(sb + 32768 + buf * 16384 + swz(r, s, 128),
                 Bt + (size_t)(col0 + r) * 1024 + k0 + s * 8);
            cp16(sb + 32768 + buf * 16384 + swz(r, s + 1, 128),
                 Bt + (size_t)(col0 + r) * 1024 + k0 + s * 8 + 8);
        }
    };

    fill(0, 0);
    CP_COMMIT();

    for (int kb = 0; kb < 16; kb++) {
        CP_WAIT(0);
        __syncthreads();
        if (kb < 15) { fill((kb + 1) & 1, (kb + 1) * 64); CP_COMMIT(); }
        const uint32_t ab = sb + (kb & 1) * 16384;
        const uint32_t bb = sb + 32768 + (kb & 1) * 16384;
#pragma unroll
        for (int ks = 0; ks < 4; ks++) {
            uint32_t a[4][4], b[2][4];
#pragma unroll
            for (int mt = 0; mt < 4; mt++) {
                int row = wm * 64 + mt * 16 + arow_l;
                ldsm4(a[mt], ab + swz(row, 2 * ks + asel, 128));
            }
#pragma unroll
            for (int pr = 0; pr < 2; pr++) {
                int row = wn * 32 + pr * 16 + brow_l;
                ldsm4(b[pr], bb + swz(row, 2 * ks + bsel, 128));
            }
#pragma unroll
            for (int mt = 0; mt < 4; mt++)
#pragma unroll
                for (int nt = 0; nt < 4; nt++)
                    mma16(acc[mt][nt], a[mt], &b[nt >> 1][(nt & 1) * 2]);
        }
    }

    if (MODE == 0) {
        const int which = col0 >> 10;          // 0=q 1=k 2=v
        const int h = (col0 & 1023) >> 7;
#pragma unroll
        for (int mt = 0; mt < 4; mt++)
#pragma unroll
            for (int nt = 0; nt < 4; nt++) {
                int col = col0 + wn * 32 + nt * 8 + 2 * l4;
                int dd = col & 127;
#pragma unroll
                for (int hf = 0; hf < 2; hf++) {
                    int gr = m0 + wm * 64 + mt * 16 + g + 8 * hf;
                    int bb2 = gr >> 12, n = gr & 4095;
                    int bh = bb2 * HEADS + h;
                    float c0 = acc[mt][nt][hf * 2], c1 = acc[mt][nt][hf * 2 + 1];
                    size_t off = ((size_t)bh * NN + n) * DH + dd;
                    if (which == 0)     // pre-scale q by 2^-5 * log2(e)
                        *(uint32_t*)(g_q + off) =
                            packh2(c0 * ATT_SCALE_L2, c1 * ATT_SCALE_L2);
                    else if (which == 1)
                        *(uint32_t*)(g_k + off) = packh2(c0, c1);
                    else                // V now row-major too (coalesced!)
                        *(uint32_t*)(g_v + off) = packh2(c0, c1);
                }
            }
    } else {
#pragma unroll
        for (int mt = 0; mt < 4; mt++)
#pragma unroll
            for (int nt = 0; nt < 4; nt++) {
                int col = col0 + wn * 32 + nt * 8 + 2 * l4;
                float2 bv = *(const float2*)(bias + col);
#pragma unroll
                for (int hf = 0; hf < 2; hf++) {
                    int gr = m0 + wm * 64 + mt * 16 + g + 8 * hf;
                    *(float2*)(out + (size_t)gr * 1024 + col) =
                        make_float2(acc[mt][nt][hf * 2] + bv.x,
                                    acc[mt][nt][hf * 2 + 1] + bv.y);
                }
            }
    }
}

// ================= Flash attention fp16 (R11 + ldmatrix.trans V) ==============
// i-tile 64, 128 threads (4 warps), 2 CTAs/SM. Warp w owns rows 16w..16w+15.
// Q frags in registers; P register-direct; exp2 softmax; K+V double-buffered.
// V stored row-major [j][d] like K; PV B-fragments via ldmatrix.x4.trans.
#define QS_OFF   0
#define K_OFF(b) (16384 + (b) * 16384)
#define V_OFF(b) (49152 + (b) * 16384)
#define ATT_SMEM 81920

__global__ __launch_bounds__(128, 2) void attn_kernel(const int* __restrict__ mask)
{
    extern __shared__ char sm[];
    const uint32_t sb = smem_u32(sm);

    const int tid = threadIdx.x, lane = tid & 31, wid = tid >> 5;
    const int g = lane >> 2, l4 = lane & 3;
    const int i0 = blockIdx.x * 64;
    const int bh = blockIdx.y;

    const __half* qP = g_q + (size_t)bh * NN * DH;
    const __half* kP = g_k + (size_t)bh * NN * DH;
    const __half* vP = g_v + (size_t)bh * NN * DH;

    const int arow_l = lane & 15;
    const int asel = (lane >> 4) & 1;
    const int brow_l = (lane & 7) + ((lane >> 4) & 1) * 8;
    const int bsel = (lane >> 3) & 1;
    // trans-ldsm lane map for V: rows = j (k-dim), cols = d
    const int vrow_l = lane & 15;        // j within 16-row chunk
    const int vsel  = (lane >> 4) & 1;   // d 8-col half (16B)

    auto fillK = [&](int buf, int j0) {           // 64 rows x 16 slots
#pragma unroll
        for (int i = 0; i < 8; i++) {
            int p = tid + i * 128;
            int r = p >> 4, s = p & 15;
            cp16(sb + K_OFF(buf) + swz(r, s, 256),
                 kP + (size_t)(j0 + r) * DH + s * 8);
        }
    };
    auto fillV = [&](int buf, int j0) {           // 64 rows x 16 slots (row-major j)
#pragma unroll
        for (int i = 0; i < 8; i++) {
            int p = tid + i * 128;
            int r = p >> 4, s = p & 15;
            cp16(sb + V_OFF(buf) + swz(r, s, 256),
                 vP + (size_t)(j0 + r) * DH + s * 8);
        }
    };

    // Q fill: 64 rows x 16 slots
#pragma unroll
    for (int i = 0; i < 8; i++) {
        int p = tid + i * 128;
        int r = p >> 4, s = p & 15;
        cp16(sb + QS_OFF + swz(r, s, 256), qP + (size_t)(i0 + r) * DH + s * 8);
    }
    fillK(0, 0);
    fillV(0, 0);
    CP_COMMIT();

    uint32_t qf[8][4];   // Q fragments, resident for whole kernel
    float oacc[16][4];
#pragma unroll
    for (int nt = 0; nt < 16; nt++)
#pragma unroll
        for (int r = 0; r < 4; r++) oacc[nt][r] = 0.f;
    float mreg[2] = {-1e30f, -1e30f};
    float lreg[2] = {0.f, 0.f};

    for (int jt = 0; jt < 64; jt++) {
        const int j0 = jt * 64;
        CP_WAIT(0);
        __syncthreads();

        if (jt == 0) {   // one-time: hoist Q fragments to registers
#pragma unroll
            for (int ks = 0; ks < 8; ks++)
                ldsm4(qf[ks], sb + QS_OFF + swz(wid * 16 + arow_l, 2 * ks + asel, 256));
        }
        if (jt < 63) {
            fillK((jt + 1) & 1, j0 + 64);
            fillV((jt + 1) & 1, j0 + 64);
            CP_COMMIT();
        }

        // ---- S = (Q*2^-5*log2e) K^T : 16 rows x 64 j, k=128 (8 x k16) ----
        float sacc[8][4];
#pragma unroll
        for (int nt = 0; nt < 8; nt++)
#pragma unroll
            for (int r = 0; r < 4; r++) sacc[nt][r] = 0.f;

        const uint32_t kb = sb + K_OFF(jt & 1);
#pragma unroll
        for (int ks = 0; ks < 8; ks++) {
            uint32_t b[4][4];
#pragma unroll
            for (int pr = 0; pr < 4; pr++)
                ldsm4(b[pr], kb + swz(pr * 16 + brow_l, 2 * ks + bsel, 256));
#pragma unroll
            for (int nt = 0; nt < 8; nt++)
                mma16(sacc[nt], qf[ks], &b[nt >> 1][(nt & 1) * 2]);
        }

        // ---- mask (S in log2 domain) ----
        if (i0 < MAXMASK && j0 < MAXMASK) {
#pragma unroll
            for (int hf = 0; hf < 2; hf++) {
                int gi = i0 + wid * 16 + g + 8 * hf;
                const int* mp = mask + (size_t)gi * MAXMASK + j0;
#pragma unroll
                for (int nt = 0; nt < 8; nt++) {
                    int2 mv = *(const int2*)(mp + nt * 8 + 2 * l4);
                    if (mv.x == 0) sacc[nt][hf * 2]     = -INFINITY;
                    if (mv.y == 0) sacc[nt][hf * 2 + 1] = -INFINITY;
                }
            }
        }

        // ---- softmax (exp2 domain), P stays in registers ----
#pragma unroll
        for (int hf = 0; hf < 2; hf++) {
            float pm = -INFINITY;
#pragma unroll
            for (int nt = 0; nt < 8; nt++)
                pm = fmaxf(pm, fmaxf(sacc[nt][hf * 2], sacc[nt][hf * 2 + 1]));
            pm = fmaxf(pm, __shfl_xor_sync(0xffffffffu, pm, 1));
            pm = fmaxf(pm, __shfl_xor_sync(0xffffffffu, pm, 2));
            float mc = fmaxf(fmaxf(mreg[hf], pm), -1e30f);
            float corr = ex2f(mreg[hf] - mc);
            mreg[hf] = mc;
            float rs = 0.f;
#pragma unroll
            for (int nt = 0; nt < 8; nt++) {
                float p0 = ex2f(sacc[nt][hf * 2]     - mc);
                float p1 = ex2f(sacc[nt][hf * 2 + 1] - mc);
                sacc[nt][hf * 2] = p0; sacc[nt][hf * 2 + 1] = p1;
                rs += p0 + p1;
            }
            rs += __shfl_xor_sync(0xffffffffu, rs, 1);
            rs += __shfl_xor_sync(0xffffffffu, rs, 2);
            lreg[hf] = lreg[hf] * corr + rs;
            if (__any_sync(0xffffffffu, corr != 1.0f)) {
#pragma unroll
                for (int nt = 0; nt < 16; nt++) {
                    oacc[nt][hf * 2]     *= corr;
                    oacc[nt][hf * 2 + 1] *= corr;
                }
            }
        }

        // ---- P C-fragments -> A-fragments (pure register pack) ----
        uint32_t pa[4][4];
#pragma unroll
        for (int ks2 = 0; ks2 < 4; ks2++) {
            pa[ks2][0] = packh2(sacc[2 * ks2][0],     sacc[2 * ks2][1]);
            pa[ks2][1] = packh2(sacc[2 * ks2][2],     sacc[2 * ks2][3]);
            pa[ks2][2] = packh2(sacc[2 * ks2 + 1][0], sacc[2 * ks2 + 1][1]);
            pa[ks2][3] = packh2(sacc[2 * ks2 + 1][2], sacc[2 * ks2 + 1][3]);
        }

        // ---- O += P V : 16 rows x 128 d, k=64 (4 x k16), V via ldsm.trans ----
        const uint32_t vb = sb + V_OFF(jt & 1);
#pragma unroll
        for (int ks2 = 0; ks2 < 4; ks2++) {
            uint32_t b[8][4];
#pragma unroll
            for (int pr = 0; pr < 8; pr++)
                ldsm4t(b[pr], vb + swz(ks2 * 16 + vrow_l, 2 * pr + vsel, 256));
#pragma unroll
            for (int nt = 0; nt < 16; nt++)
                mma16(oacc[nt], pa[ks2], &b[nt >> 1][(nt & 1) * 2]);
        }
    }

    // ---- finalize (fp16 for out-proj consumption) ----
    const int b = bh >> 3, h = bh & 7;
#pragma unroll
    for (int hf = 0; hf < 2; hf++) {
        float inv = 1.f / lreg[hf];
        int gi = i0 + wid * 16 + g + 8 * hf;
        size_t base = ((size_t)(b * NN + gi)) * 1024 + h * DH;
#pragma unroll
        for (int nt = 0; nt < 16; nt++)
            *(uint32_t*)(g_att + base + nt * 8 + 2 * l4) =
                packh2(oacc[nt][hf * 2] * inv, oacc[nt][hf * 2 + 1] * inv);
    }
}

// ---------------- launcher ----------------
extern "C" void kernel_launch(void* const* d_in, const int* in_sizes, int n_in,
                              void* d_out, int out_size)
{
    const float* x     = (const float*)d_in[0];
    const float* W_qkv = (const float*)d_in[1];
    const float* W_out = (const float*)d_in[2];
    const float* b_out = (const float*)d_in[3];
    const int*   mask  = (const int*)  d_in[4];
    float* out = (float*)d_out;

    cudaFuncSetAttribute(attn_kernel,
                         cudaFuncAttributeMaxDynamicSharedMemorySize, ATT_SMEM);
    cudaFuncSetAttribute(mma_gemm<0>,
                         cudaFuncAttributeMaxDynamicSharedMemorySize, GEMM_SMEM);
    cudaFuncSetAttribute(mma_gemm<1>,
                         cudaFuncAttributeMaxDynamicSharedMemorySize, GEMM_SMEM);

    __half* xh;    cudaGetSymbolAddress((void**)&xh, g_xh);
    __half* wqkvT; cudaGetSymbolAddress((void**)&wqkvT, g_wqkvT);
    __half* woutT; cudaGetSymbolAddress((void**)&woutT, g_woutT);
    __half* att;   cudaGetSymbolAddress((void**)&att, g_att);

    conv_x<<<4096, 256>>>(x, xh);
    transpose_k<<<dim3(96, 32), dim3(32, 8)>>>(W_qkv, wqkvT, 1024, 3072);
    transpose_k<<<dim3(32, 32), dim3(32, 8)>>>(W_out, woutT, 1024, 1024);

    mma_gemm<0><<<dim3(24, 64), 256, GEMM_SMEM>>>(xh, wqkvT, nullptr, nullptr);
    attn_kernel<<<dim3(64, 16), 128, ATT_SMEM>>>(mask);
    mma_gemm<1><<<dim3(8, 64), 256, GEMM_SMEM>>>(att, woutT, b_out, out);
}

// round 17
// speedup vs baseline: 1.0281x; 1.0206x over previous
#include <cuda_runtime.h>
#include <cuda_fp16.h>
#include <math.h>
#include <stdint.h>

#define NN 4096
#define HEADS 8
#define DH 128
#define MAXMASK 2048
// attention scale folded with log2(e): softmax done in exp2 domain
#define ATT_SCALE_L2 (0.03125f * 1.44269504f)

// ---------------- scratch (fp16 operands everywhere) ----------------
__device__ __half g_xh [(size_t)8192*1024];   // x in fp16
__device__ __half g_q  [(size_t)16*NN*DH];    // [bh][n][d], pre-scaled by 2^-5*log2e
__device__ __half g_k  [(size_t)16*NN*DH];    // [bh][n][d]
__device__ __half g_vT [(size_t)16*DH*NN];    // [bh][d][n]
__device__ __half g_att[(size_t)8192*1024];   // [b*n][dim]
__device__ __half g_wqkvT[(size_t)3072*1024]; // W_qkv^T fp16
__device__ __half g_woutT[(size_t)1024*1024]; // W_out^T fp16

// ---------------- helpers ----------------
__device__ __forceinline__ uint32_t smem_u32(const void* p) {
    uint32_t a;
    asm("{ .reg .u64 t; cvta.to.shared.u64 t, %1; cvt.u32.u64 %0, t; }"
        : "=r"(a) : "l"(p));
    return a;
}
__device__ __forceinline__ void cp16(uint32_t sdst, const void* gsrc) {
    asm volatile("cp.async.cg.shared.global [%0], [%1], 16;"
                 :: "r"(sdst), "l"(gsrc) : "memory");
}
#define CP_COMMIT() asm volatile("cp.async.commit_group;" ::: "memory")
#define CP_WAIT(n)  asm volatile("cp.async.wait_group %0;" :: "n"(n) : "memory")

__device__ __forceinline__ void ldsm4(uint32_t* r, uint32_t saddr) {
    asm volatile("ldmatrix.sync.aligned.m8n8.x4.shared.b16 {%0,%1,%2,%3}, [%4];"
        : "=r"(r[0]), "=r"(r[1]), "=r"(r[2]), "=r"(r[3]) : "r"(saddr));
}
__device__ __forceinline__ void mma16(float* d, const uint32_t* a, const uint32_t* b) {
    asm volatile(
        "mma.sync.aligned.m16n8k16.row.col.f32.f16.f16.f32 "
        "{%0,%1,%2,%3}, {%4,%5,%6,%7}, {%8,%9}, {%0,%1,%2,%3};"
        : "+f"(d[0]), "+f"(d[1]), "+f"(d[2]), "+f"(d[3])
        : "r"(a[0]), "r"(a[1]), "r"(a[2]), "r"(a[3]), "r"(b[0]), "r"(b[1]));
}
__device__ __forceinline__ uint32_t swz(int row, int slot, int rowb) {
    return (uint32_t)(row * rowb + ((slot ^ (row & 7)) << 4));
}
__device__ __forceinline__ uint32_t packh2(float a, float b) {
    __half2 h = __floats2half2_rn(a, b);
    return *(uint32_t*)&h;
}
__device__ __forceinline__ float ex2f(float x) {
    float r;
    asm("ex2.approx.ftz.f32 %0, %1;" : "=f"(r) : "f"(x));
    return r;
}

// ---------------- convert x to fp16 ----------------
__global__ void conv_x(const float* __restrict__ in, __half* __restrict__ outp)
{
    size_t i = ((size_t)blockIdx.x * blockDim.x + threadIdx.x) * 8;
    float4 v0 = *(const float4*)(in + i);
    float4 v1 = *(const float4*)(in + i + 4);
    uint4 o;
    o.x = packh2(v0.x, v0.y); o.y = packh2(v0.z, v0.w);
    o.z = packh2(v1.x, v1.y); o.w = packh2(v1.z, v1.w);
    *(uint4*)(outp + i) = o;
}

// ---------------- weight transpose + fp16 convert ----------------
__global__ void transpose_k(const float* __restrict__ in, __half* __restrict__ outp,
                            int R, int C)
{
    __shared__ float t[32][33];
    int bx = blockIdx.x * 32, by = blockIdx.y * 32;
    int tx = threadIdx.x, ty = threadIdx.y;  // 32 x 8
#pragma unroll
    for (int i = 0; i < 32; i += 8)
        t[ty + i][tx] = in[(size_t)(by + ty + i) * C + bx + tx];
    __syncthreads();
#pragma unroll
    for (int i = 0; i < 32; i += 8)
        outp[(size_t)(bx + ty + i) * R + by + tx] = __float2half(t[tx][ty + i]);
}

// ================= fp16 GEMM (R11 2-stage, known-good) ========================
#define GEMM_SMEM 65536
template<int MODE>
__global__ __launch_bounds__(256, 2) void mma_gemm(
    const __half* __restrict__ A, const __half* __restrict__ Bt,
    const float* __restrict__ bias, float* __restrict__ out)
{
    extern __shared__ char sm[];
    const uint32_t sb = smem_u32(sm);
    const int tid = threadIdx.x, lane = tid & 31, wid = tid >> 5;
    const int wm = wid >> 2, wn = wid & 3;
    const int g = lane >> 2, l4 = lane & 3;
    const int m0 = blockIdx.y * 128, col0 = blockIdx.x * 128;

    const int arow_l = lane & 15;
    const int asel = (lane >> 4) & 1;
    const int brow_l = (lane & 7) + ((lane >> 4) & 1) * 8;
    const int bsel = (lane >> 3) & 1;

    float acc[4][4][4];
#pragma unroll
    for (int mt = 0; mt < 4; mt++)
#pragma unroll
        for (int nt = 0; nt < 4; nt++)
#pragma unroll
            for (int r = 0; r < 4; r++) acc[mt][nt][r] = 0.f;

    auto fill = [&](int buf, int k0) {
#pragma unroll
        for (int i = 0; i < 2; i++) {
            int p = tid + i * 256;
            int r = p >> 2, s = (p & 3) * 2;
            cp16(sb + buf * 16384 + swz(r, s, 128),
                 A + (size_t)(m0 + r) * 1024 + k0 + s * 8);
            cp16(sb + buf * 16384 + swz(r, s + 1, 128),
                 A + (size_t)(m0 + r) * 1024 + k0 + s * 8 + 8);
        }
#pragma unroll
        for (int i = 0; i < 2; i++) {
            int p = tid + i * 256;
            int r = p >> 2, s = (p & 3) * 2;
            cp16(sb + 32768 + buf * 16384 + swz(r, s, 128),
                 Bt + (size_t)(col0 + r) * 1024 + k0 + s * 8);
            cp16(sb + 32768 + buf * 16384 + swz(r, s + 1, 128),
                 Bt + (size_t)(col0 + r) * 1024 + k0 + s * 8 + 8);
        }
    };

    fill(0, 0);
    CP_COMMIT();

    for (int kb = 0; kb < 16; kb++) {
        CP_WAIT(0);
        __syncthreads();
        if (kb < 15) { fill((kb + 1) & 1, (kb + 1) * 64); CP_COMMIT(); }
        const uint32_t ab = sb + (kb & 1) * 16384;
        const uint32_t bb = sb + 32768 + (kb & 1) * 16384;
#pragma unroll
        for (int ks = 0; ks < 4; ks++) {
            uint32_t a[4][4], b[2][4];
#pragma unroll
            for (int mt = 0; mt < 4; mt++) {
                int row = wm * 64 + mt * 16 + arow_l;
                ldsm4(a[mt], ab + swz(row, 2 * ks + asel, 128));
            }
#pragma unroll
            for (int pr = 0; pr < 2; pr++) {
                int row = wn * 32 + pr * 16 + brow_l;
                ldsm4(b[pr], bb + swz(row, 2 * ks + bsel, 128));
            }
#pragma unroll
            for (int mt = 0; mt < 4; mt++)
#pragma unroll
                for (int nt = 0; nt < 4; nt++)
                    mma16(acc[mt][nt], a[mt], &b[nt >> 1][(nt & 1) * 2]);
        }
    }

    if (MODE == 0) {
        const int which = col0 >> 10;          // 0=q 1=k 2=v
        const int h = (col0 & 1023) >> 7;
#pragma unroll
        for (int mt = 0; mt < 4; mt++)
#pragma unroll
            for (int nt = 0; nt < 4; nt++) {
                int col = col0 + wn * 32 + nt * 8 + 2 * l4;
                int dd = col & 127;
#pragma unroll
                for (int hf = 0; hf < 2; hf++) {
                    int gr = m0 + wm * 64 + mt * 16 + g + 8 * hf;
                    int bb2 = gr >> 12, n = gr & 4095;
                    int bh = bb2 * HEADS + h;
                    float c0 = acc[mt][nt][hf * 2], c1 = acc[mt][nt][hf * 2 + 1];
                    if (which == 0)     // pre-scale q by 2^-5 * log2(e)
                        *(uint32_t*)(g_q + ((size_t)bh * NN + n) * DH + dd) =
                            packh2(c0 * ATT_SCALE_L2, c1 * ATT_SCALE_L2);
                    else if (which == 1)
                        *(uint32_t*)(g_k + ((size_t)bh * NN + n) * DH + dd) = packh2(c0, c1);
                    else {
                        __half* dst = g_vT + ((size_t)bh * DH + dd) * NN + n;
                        dst[0] = __float2half(c0); dst[NN] = __float2half(c1);
                    }
                }
            }
    } else {
#pragma unroll
        for (int mt = 0; mt < 4; mt++)
#pragma unroll
            for (int nt = 0; nt < 4; nt++) {
                int col = col0 + wn * 32 + nt * 8 + 2 * l4;
                float2 bv = *(const float2*)(bias + col);
#pragma unroll
                for (int hf = 0; hf < 2; hf++) {
                    int gr = m0 + wm * 64 + mt * 16 + g + 8 * hf;
                    *(float2*)(out + (size_t)gr * 1024 + col) =
                        make_float2(acc[mt][nt][hf * 2] + bv.x,
                                    acc[mt][nt][hf * 2 + 1] + bv.y);
                }
            }
    }
}

// ================= Flash attention fp16 (R11 + reg-pipelined S loop) ==========
// i-tile 64, 128 threads (4 warps), 2 CTAs/SM. Warp w owns rows 16w..16w+15.
// Q frags in registers; P register-direct; exp2 softmax; K+V double-buffered.
// S loop: K b-fragments double-buffered in registers (ldsm of ks+1 issued
// before the MMAs of ks) to hide LDS latency at each k-step boundary.
#define QS_OFF   0
#define K_OFF(b) (16384 + (b) * 16384)
#define V_OFF(b) (49152 + (b) * 16384)
#define ATT_SMEM 81920

__global__ __launch_bounds__(128, 2) void attn_kernel(const int* __restrict__ mask)
{
    extern __shared__ char sm[];
    const uint32_t sb = smem_u32(sm);

    const int tid = threadIdx.x, lane = tid & 31, wid = tid >> 5;
    const int g = lane >> 2, l4 = lane & 3;
    const int i0 = blockIdx.x * 64;
    const int bh = blockIdx.y;

    const __half* qP  = g_q  + (size_t)bh * NN * DH;
    const __half* kP  = g_k  + (size_t)bh * NN * DH;
    const __half* vTP = g_vT + (size_t)bh * DH * NN;

    const int arow_l = lane & 15;
    const int asel = (lane >> 4) & 1;
    const int brow_l = (lane & 7) + ((lane >> 4) & 1) * 8;
    const int bsel = (lane >> 3) & 1;

    auto fillK = [&](int buf, int j0) {           // 64 rows x 16 slots
#pragma unroll
        for (int i = 0; i < 8; i++) {
            int p = tid + i * 128;
            int r = p >> 4, s = p & 15;
            cp16(sb + K_OFF(buf) + swz(r, s, 256),
                 kP + (size_t)(j0 + r) * DH + s * 8);
        }
    };
    auto fillV = [&](int buf, int j0) {           // 128 d-rows x 8 slots
#pragma unroll
        for (int i = 0; i < 8; i++) {
            int p = tid + i * 128;
            int r = p >> 3, s = p & 7;
            cp16(sb + V_OFF(buf) + swz(r, s, 128),
                 vTP + (size_t)r * NN + j0 + s * 8);
        }
    };

    // Q fill: 64 rows x 16 slots
#pragma unroll
    for (int i = 0; i < 8; i++) {
        int p = tid + i * 128;
        int r = p >> 4, s = p & 15;
        cp16(sb + QS_OFF + swz(r, s, 256), qP + (size_t)(i0 + r) * DH + s * 8);
    }
    fillK(0, 0);
    fillV(0, 0);
    CP_COMMIT();

    uint32_t qf[8][4];   // Q fragments, resident for whole kernel
    float oacc[16][4];
#pragma unroll
    for (int nt = 0; nt < 16; nt++)
#pragma unroll
        for (int r = 0; r < 4; r++) oacc[nt][r] = 0.f;
    float mreg[2] = {-1e30f, -1e30f};
    float lreg[2] = {0.f, 0.f};

    for (int jt = 0; jt < 64; jt++) {
        const int j0 = jt * 64;
        CP_WAIT(0);
        __syncthreads();

        if (jt == 0) {   // one-time: hoist Q fragments to registers
#pragma unroll
            for (int ks = 0; ks < 8; ks++)
                ldsm4(qf[ks], sb + QS_OFF + swz(wid * 16 + arow_l, 2 * ks + asel, 256));
        }
        if (jt < 63) {
            fillK((jt + 1) & 1, j0 + 64);
            fillV((jt + 1) & 1, j0 + 64);
            CP_COMMIT();
        }

        // ---- S = (Q*2^-5*log2e) K^T : 16 rows x 64 j, k=128 (8 x k16) ----
        // K b-fragments register-double-buffered across ks.
        float sacc[8][4];
#pragma unroll
        for (int nt = 0; nt < 8; nt++)
#pragma unroll
            for (int r = 0; r < 4; r++) sacc[nt][r] = 0.f;

        const uint32_t kb = sb + K_OFF(jt & 1);
        uint32_t bf[2][4][4];
#pragma unroll
        for (int pr = 0; pr < 4; pr++)
            ldsm4(bf[0][pr], kb + swz(pr * 16 + brow_l, bsel, 256));
#pragma unroll
        for (int ks = 0; ks < 8; ks++) {
            const int cur = ks & 1;
            if (ks < 7) {
#pragma unroll
                for (int pr = 0; pr < 4; pr++)
                    ldsm4(bf[cur ^ 1][pr],
                          kb + swz(pr * 16 + brow_l, 2 * (ks + 1) + bsel, 256));
            }
#pragma unroll
            for (int nt = 0; nt < 8; nt++)
                mma16(sacc[nt], qf[ks], &bf[cur][nt >> 1][(nt & 1) * 2]);
        }

        // ---- mask (S in log2 domain) ----
        if (i0 < MAXMASK && j0 < MAXMASK) {
#pragma unroll
            for (int hf = 0; hf < 2; hf++) {
                int gi = i0 + wid * 16 + g + 8 * hf;
                const int* mp = mask + (size_t)gi * MAXMASK + j0;
#pragma unroll
                for (int nt = 0; nt < 8; nt++) {
                    int2 mv = *(const int2*)(mp + nt * 8 + 2 * l4);
                    if (mv.x == 0) sacc[nt][hf * 2]     = -INFINITY;
                    if (mv.y == 0) sacc[nt][hf * 2 + 1] = -INFINITY;
                }
            }
        }

        // ---- softmax (exp2 domain), P stays in registers ----
#pragma unroll
        for (int hf = 0; hf < 2; hf++) {
            float pm = -INFINITY;
#pragma unroll
            for (int nt = 0; nt < 8; nt++)
                pm = fmaxf(pm, fmaxf(sacc[nt][hf * 2], sacc[nt][hf * 2 + 1]));
            pm = fmaxf(pm, __shfl_xor_sync(0xffffffffu, pm, 1));
            pm = fmaxf(pm, __shfl_xor_sync(0xffffffffu, pm, 2));
            float mc = fmaxf(fmaxf(mreg[hf], pm), -1e30f);
            float corr = ex2f(mreg[hf] - mc);
            mreg[hf] = mc;
            float rs = 0.f;
#pragma unroll
            for (int nt = 0; nt < 8; nt++) {
                float p0 = ex2f(sacc[nt][hf * 2]     - mc);
                float p1 = ex2f(sacc[nt][hf * 2 + 1] - mc);
                sacc[nt][hf * 2] = p0; sacc[nt][hf * 2 + 1] = p1;
                rs += p0 + p1;
            }
            rs += __shfl_xor_sync(0xffffffffu, rs, 1);
            rs += __shfl_xor_sync(0xffffffffu, rs, 2);
            lreg[hf] = lreg[hf] * corr + rs;
            if (__any_sync(0xffffffffu, corr != 1.0f)) {
#pragma unroll
                for (int nt = 0; nt < 16; nt++) {
                    oacc[nt][hf * 2]     *= corr;
                    oacc[nt][hf * 2 + 1] *= corr;
                }
            }
        }

        // ---- P C-fragments -> A-fragments (pure register pack) ----
        uint32_t pa[4][4];
#pragma unroll
        for (int ks2 = 0; ks2 < 4; ks2++) {
            pa[ks2][0] = packh2(sacc[2 * ks2][0],     sacc[2 * ks2][1]);
            pa[ks2][1] = packh2(sacc[2 * ks2][2],     sacc[2 * ks2][3]);
            pa[ks2][2] = packh2(sacc[2 * ks2 + 1][0], sacc[2 * ks2 + 1][1]);
            pa[ks2][3] = packh2(sacc[2 * ks2 + 1][2], sacc[2 * ks2 + 1][3]);
        }

        // ---- O += P V : 16 rows x 128 d, k=64 (4 x k16) ----
        const uint32_t vb = sb + V_OFF(jt & 1);
#pragma unroll
        for (int ks2 = 0; ks2 < 4; ks2++) {
            uint32_t b[8][4];
#pragma unroll
            for (int pr = 0; pr < 8; pr++)
                ldsm4(b[pr], vb + swz(pr * 16 + brow_l, 2 * ks2 + bsel, 128));
#pragma unroll
            for (int nt = 0; nt < 16; nt++)
                mma16(oacc[nt], pa[ks2], &b[nt >> 1][(nt & 1) * 2]);
        }
    }

    // ---- finalize (fp16 for out-proj consumption) ----
    const int b = bh >> 3, h = bh & 7;
#pragma unroll
    for (int hf = 0; hf < 2; hf++) {
        float inv = 1.f / lreg[hf];
        int gi = i0 + wid * 16 + g + 8 * hf;
        size_t base = ((size_t)(b * NN + gi)) * 1024 + h * DH;
#pragma unroll
        for (int nt = 0; nt < 16; nt++)
            *(uint32_t*)(g_att + base + nt * 8 + 2 * l4) =
                packh2(oacc[nt][hf * 2] * inv, oacc[nt][hf * 2 + 1] * inv);
    }
}

// ---------------- launcher ----------------
extern "C" void kernel_launch(void* const* d_in, const int* in_sizes, int n_in,
                              void* d_out, int out_size)
{
    const float* x     = (const float*)d_in[0];
    const float* W_qkv = (const float*)d_in[1];
    const float* W_out = (const float*)d_in[2];
    const float* b_out = (const float*)d_in[3];
    const int*   mask  = (const int*)  d_in[4];
    float* out = (float*)d_out;

    cudaFuncSetAttribute(attn_kernel,
                         cudaFuncAttributeMaxDynamicSharedMemorySize, ATT_SMEM);
    cudaFuncSetAttribute(mma_gemm<0>,
                         cudaFuncAttributeMaxDynamicSharedMemorySize, GEMM_SMEM);
    cudaFuncSetAttribute(mma_gemm<1>,
                         cudaFuncAttributeMaxDynamicSharedMemorySize, GEMM_SMEM);

    __half* xh;    cudaGetSymbolAddress((void**)&xh, g_xh);
    __half* wqkvT; cudaGetSymbolAddress((void**)&wqkvT, g_wqkvT);
    __half* woutT; cudaGetSymbolAddress((void**)&woutT, g_woutT);
    __half* att;   cudaGetSymbolAddress((void**)&att, g_att);

    conv_x<<<4096, 256>>>(x, xh);
    transpose_k<<<dim3(96, 32), dim3(32, 8)>>>(W_qkv, wqkvT, 1024, 3072);
    transpose_k<<<dim3(32, 32), dim3(32, 8)>>>(W_out, woutT, 1024, 1024);

    mma_gemm<0><<<dim3(24, 64), 256, GEMM_SMEM>>>(xh, wqkvT, nullptr, nullptr);
    attn_kernel<<<dim3(64, 16), 128, ATT_SMEM>>>(mask);
    mma_gemm<1><<<dim3(8, 64), 256, GEMM_SMEM>>>(att, woutT, b_out, out);
}